// round 2
// baseline (speedup 1.0000x reference)
#include <cuda_runtime.h>

#define HW   16384        // 128*128
#define CIN  256
#define NB   4
#define WDIM 128

// Scratch (allocation-free rule: __device__ globals)
__device__ float g_value[(size_t)NB * 256 * HW];   // 64 MB
__device__ float g_hbuf [(size_t)NB * 256 * HW];   // 64 MB
__device__ float g_flow [(size_t)NB * 64  * HW];   // 16 MB

// ---------------------------------------------------------------------------
// Fused conv GEMM: computes value = wv@u + bv  (mblk 0,1)
//                  and      h    = relu(w1@u + b1)  (mblk 2,3)
// Tile: BM=128, BN=128, BK=16, 256 threads, 8x8 per-thread microtile.
// ---------------------------------------------------------------------------
__global__ __launch_bounds__(256)
void conv_gemm_kernel(const float* __restrict__ u,
                      const float* __restrict__ w1, const float* __restrict__ b1,
                      const float* __restrict__ wv, const float* __restrict__ bv)
{
    __shared__ float As[2][16][132];   // [k][m], padded
    __shared__ float Bs[2][16][128];   // [k][n]

    const int tid  = threadIdx.x;
    const int bz   = blockIdx.z;
    const int nblk = blockIdx.x;          // pixel tile
    const int mblk = blockIdx.y;          // 0..3
    const bool is_h = (mblk >= 2);
    const float* W  = is_h ? w1 : wv;
    const int mrow0 = (mblk & 1) * 128;   // row offset inside the 256-row weight
    const float* U  = u + (size_t)bz * CIN * HW + nblk * 128;

    // A-load mapping: 128 rows x 16 k, 2 float4 per thread
    const int ar = tid >> 2;              // 0..63
    const int ac = (tid & 3) * 4;         // 0,4,8,12
    // B-load mapping: 16 k x 128 n, 2 float4 per thread
    const int bk = tid >> 5;              // 0..7
    const int bn = (tid & 31) * 4;        // 0..124

    const int tx = tid & 15;
    const int ty = tid >> 4;

    float acc[8][8];
#pragma unroll
    for (int i = 0; i < 8; i++)
#pragma unroll
        for (int j = 0; j < 8; j++) acc[i][j] = 0.f;

    float4 aR0, aR1, bR0, bR1;

    // prologue: tile 0
    {
        const float* Ap = W + (size_t)(mrow0 + ar) * CIN + ac;
        aR0 = *(const float4*)Ap;
        aR1 = *(const float4*)(Ap + (size_t)64 * CIN);
        const float* Bp = U + (size_t)bk * HW + bn;
        bR0 = *(const float4*)Bp;
        bR1 = *(const float4*)(Bp + (size_t)8 * HW);
    }
    {
        As[0][ac+0][ar] = aR0.x; As[0][ac+1][ar] = aR0.y;
        As[0][ac+2][ar] = aR0.z; As[0][ac+3][ar] = aR0.w;
        As[0][ac+0][ar+64] = aR1.x; As[0][ac+1][ar+64] = aR1.y;
        As[0][ac+2][ar+64] = aR1.z; As[0][ac+3][ar+64] = aR1.w;
        *(float4*)&Bs[0][bk  ][bn] = bR0;
        *(float4*)&Bs[0][bk+8][bn] = bR1;
    }
    __syncthreads();

    int buf = 0;
#pragma unroll 1
    for (int kt = 0; kt < 16; kt++) {
        if (kt + 1 < 16) {
            const int k0 = (kt + 1) * 16;
            const float* Ap = W + (size_t)(mrow0 + ar) * CIN + k0 + ac;
            aR0 = *(const float4*)Ap;
            aR1 = *(const float4*)(Ap + (size_t)64 * CIN);
            const float* Bp = U + (size_t)(k0 + bk) * HW + bn;
            bR0 = *(const float4*)Bp;
            bR1 = *(const float4*)(Bp + (size_t)8 * HW);
        }
#pragma unroll
        for (int kk = 0; kk < 16; kk++) {
            float a[8], bb[8];
            *(float4*)&a[0]  = *(const float4*)&As[buf][kk][ty * 4];
            *(float4*)&a[4]  = *(const float4*)&As[buf][kk][64 + ty * 4];
            *(float4*)&bb[0] = *(const float4*)&Bs[buf][kk][tx * 4];
            *(float4*)&bb[4] = *(const float4*)&Bs[buf][kk][64 + tx * 4];
#pragma unroll
            for (int i = 0; i < 8; i++)
#pragma unroll
                for (int j = 0; j < 8; j++)
                    acc[i][j] = fmaf(a[i], bb[j], acc[i][j]);
        }
        if (kt + 1 < 16) {
            const int nb2 = buf ^ 1;
            As[nb2][ac+0][ar] = aR0.x; As[nb2][ac+1][ar] = aR0.y;
            As[nb2][ac+2][ar] = aR0.z; As[nb2][ac+3][ar] = aR0.w;
            As[nb2][ac+0][ar+64] = aR1.x; As[nb2][ac+1][ar+64] = aR1.y;
            As[nb2][ac+2][ar+64] = aR1.z; As[nb2][ac+3][ar+64] = aR1.w;
            *(float4*)&Bs[nb2][bk  ][bn] = bR0;
            *(float4*)&Bs[nb2][bk+8][bn] = bR1;
            buf = nb2;
            __syncthreads();
        }
    }

    // Epilogue
    const int pix0 = nblk * 128;
    float* outbuf = is_h ? g_hbuf : g_value;
    const float* bias = is_h ? b1 : bv;
    const size_t base = (size_t)bz * 256 * HW;

#pragma unroll
    for (int i = 0; i < 8; i++) {
        const int mi = mrow0 + ((i < 4) ? (ty * 4 + i) : (64 + ty * 4 + (i - 4)));
        const float bb = bias[mi];
        float r[8];
#pragma unroll
        for (int j = 0; j < 8; j++) {
            float v = acc[i][j] + bb;
            if (is_h) v = fmaxf(v, 0.f);
            r[j] = v;
        }
        float* op = outbuf + base + (size_t)mi * HW + pix0;
        *(float4*)&op[tx * 4]      = *(float4*)&r[0];
        *(float4*)&op[64 + tx * 4] = *(float4*)&r[4];
    }
}

// ---------------------------------------------------------------------------
// Flow GEMM: flow = w2 @ h + b2.  BM=64, BN=128, BK=16, 256 threads, 4x8 tile.
// ---------------------------------------------------------------------------
__global__ __launch_bounds__(256)
void flow_gemm_kernel(const float* __restrict__ w2, const float* __restrict__ b2)
{
    __shared__ float As[2][16][68];
    __shared__ float Bs[2][16][128];

    const int tid  = threadIdx.x;
    const int bz   = blockIdx.z;
    const int nblk = blockIdx.x;
    const float* U = g_hbuf + (size_t)bz * 256 * HW + nblk * 128;

    const int ar = tid >> 2;              // 0..63
    const int ac = (tid & 3) * 4;
    const int bk = tid >> 5;
    const int bn = (tid & 31) * 4;
    const int tx = tid & 15;
    const int ty = tid >> 4;              // 0..15 -> rows ty*4..+3

    float acc[4][8];
#pragma unroll
    for (int i = 0; i < 4; i++)
#pragma unroll
        for (int j = 0; j < 8; j++) acc[i][j] = 0.f;

    float4 aR0, bR0, bR1;
    {
        aR0 = *(const float4*)(w2 + (size_t)ar * CIN + ac);
        const float* Bp = U + (size_t)bk * HW + bn;
        bR0 = *(const float4*)Bp;
        bR1 = *(const float4*)(Bp + (size_t)8 * HW);
    }
    {
        As[0][ac+0][ar] = aR0.x; As[0][ac+1][ar] = aR0.y;
        As[0][ac+2][ar] = aR0.z; As[0][ac+3][ar] = aR0.w;
        *(float4*)&Bs[0][bk  ][bn] = bR0;
        *(float4*)&Bs[0][bk+8][bn] = bR1;
    }
    __syncthreads();

    int buf = 0;
#pragma unroll 1
    for (int kt = 0; kt < 16; kt++) {
        if (kt + 1 < 16) {
            const int k0 = (kt + 1) * 16;
            aR0 = *(const float4*)(w2 + (size_t)ar * CIN + k0 + ac);
            const float* Bp = U + (size_t)(k0 + bk) * HW + bn;
            bR0 = *(const float4*)Bp;
            bR1 = *(const float4*)(Bp + (size_t)8 * HW);
        }
#pragma unroll
        for (int kk = 0; kk < 16; kk++) {
            float a[4], bb[8];
            *(float4*)&a[0]  = *(const float4*)&As[buf][kk][ty * 4];
            *(float4*)&bb[0] = *(const float4*)&Bs[buf][kk][tx * 4];
            *(float4*)&bb[4] = *(const float4*)&Bs[buf][kk][64 + tx * 4];
#pragma unroll
            for (int i = 0; i < 4; i++)
#pragma unroll
                for (int j = 0; j < 8; j++)
                    acc[i][j] = fmaf(a[i], bb[j], acc[i][j]);
        }
        if (kt + 1 < 16) {
            const int nb2 = buf ^ 1;
            As[nb2][ac+0][ar] = aR0.x; As[nb2][ac+1][ar] = aR0.y;
            As[nb2][ac+2][ar] = aR0.z; As[nb2][ac+3][ar] = aR0.w;
            *(float4*)&Bs[nb2][bk  ][bn] = bR0;
            *(float4*)&Bs[nb2][bk+8][bn] = bR1;
            buf = nb2;
            __syncthreads();
        }
    }

    const int pix0 = nblk * 128;
    const size_t base = (size_t)bz * 64 * HW;
#pragma unroll
    for (int i = 0; i < 4; i++) {
        const int mi = ty * 4 + i;
        const float bb = b2[mi];
        float r[8];
#pragma unroll
        for (int j = 0; j < 8; j++) r[j] = acc[i][j] + bb;
        float* op = g_flow + base + (size_t)mi * HW + pix0;
        *(float4*)&op[tx * 4]      = *(float4*)&r[0];
        *(float4*)&op[64 + tx * 4] = *(float4*)&r[4];
    }
}

// ---------------------------------------------------------------------------
// Gather: bilinear grid-sample with zeros padding, align_corners=True.
// One thread per (x), block per (y), grid.y per (b*32+head). 8 channels/thread.
// ---------------------------------------------------------------------------
__global__ __launch_bounds__(128)
void warp_gather_kernel(float* __restrict__ out)
{
    const int x  = threadIdx.x;          // 0..127
    const int y  = blockIdx.x;           // 0..127
    const int bh = blockIdx.y;           // 0..127
    const int b  = bh >> 5;
    const int head = bh & 31;

    const float* fb = g_flow + ((size_t)b * 64 + head * 2) * HW + y * WDIM + x;
    const float fx = fb[0];
    const float fy = fb[HW];

    const float gx = fmaf((float)x, 2.f / 127.f, -1.f) + fx;
    const float gy = fmaf((float)y, 2.f / 127.f, -1.f) + fy;
    const float ix = (gx + 1.f) * 63.5f;
    const float iy = (gy + 1.f) * 63.5f;

    const float x0f = floorf(ix), y0f = floorf(iy);
    const float dx = ix - x0f, dy = iy - y0f;
    const int x0 = (int)x0f, y0 = (int)y0f;
    const int x1 = x0 + 1,   y1 = y0 + 1;

    const bool vx0 = (x0 >= 0) & (x0 < WDIM);
    const bool vx1 = (x1 >= 0) & (x1 < WDIM);
    const bool vy0 = (y0 >= 0) & (y0 < WDIM);
    const bool vy1 = (y1 >= 0) & (y1 < WDIM);

    const int x0c = min(max(x0, 0), WDIM - 1);
    const int x1c = min(max(x1, 0), WDIM - 1);
    const int y0c = min(max(y0, 0), WDIM - 1);
    const int y1c = min(max(y1, 0), WDIM - 1);

    const float w00 = (1.f - dx) * (1.f - dy) * (float)(vx0 & vy0);
    const float w01 = dx * (1.f - dy)         * (float)(vx1 & vy0);
    const float w10 = (1.f - dx) * dy         * (float)(vx0 & vy1);
    const float w11 = dx * dy                 * (float)(vx1 & vy1);

    const int p00 = y0c * WDIM + x0c;
    const int p01 = y0c * WDIM + x1c;
    const int p10 = y1c * WDIM + x0c;
    const int p11 = y1c * WDIM + x1c;

    const float* vb = g_value + ((size_t)b * 256 + head * 8) * HW;
    float* ob = out + ((size_t)b * 256 + head * 8) * HW + y * WDIM + x;

#pragma unroll
    for (int ci = 0; ci < 8; ci++) {
        const float* v = vb + (size_t)ci * HW;
        float r = w00 * v[p00] + w01 * v[p01] + w10 * v[p10] + w11 * v[p11];
        ob[(size_t)ci * HW] = r;
    }
}

// ---------------------------------------------------------------------------
extern "C" void kernel_launch(void* const* d_in, const int* in_sizes, int n_in,
                              void* d_out, int out_size)
{
    const float* u  = (const float*)d_in[0];
    const float* w1 = (const float*)d_in[1];
    const float* b1 = (const float*)d_in[2];
    const float* w2 = (const float*)d_in[3];
    const float* b2 = (const float*)d_in[4];
    const float* wv = (const float*)d_in[5];
    const float* bv = (const float*)d_in[6];
    float* out = (float*)d_out;

    conv_gemm_kernel<<<dim3(128, 4, NB), 256>>>(u, w1, b1, wv, bv);
    flow_gemm_kernel<<<dim3(128, 1, NB), 256>>>(w2, b2);
    warp_gather_kernel<<<dim3(128, 128), 128>>>(out);
}